// round 5
// baseline (speedup 1.0000x reference)
#include <cuda_runtime.h>

// Problem constants (fixed by the reference setup_inputs).
#define BB 4
#define LQ 4096
#define LK 4096
#define DD 128

#define NCH 128                   // j-chunks per batch (32 j each)
#define CHUNK_J (LK / NCH)        // 32

#define A_ITEMS 512               // sk items: 32 rows each
#define B_ITEMS (BB * NCH)        // 512: (batch, chunk)
#define ATT_ITEMS 2048            // 8 att rows each
#define OUT_ITEMS 512             // 32 out rows each
#define D_ITEMS (ATT_ITEMS + OUT_ITEMS)

// Scratch (allocation-free rule: __device__ globals).
__device__ float g_sk[BB * LK];              // raw key scores
__device__ float g_p[BB * LK];               // softmax probabilities
__device__ float g_part[BB * NCH * DD];      // partial p·val sums

// Monotonic-epoch grid barrier state (zero-init, never reset -> replay-safe).
__device__ unsigned long long g_bar_cnt[2];
__device__ volatile unsigned long long g_bar_rel[2];

__device__ __forceinline__ void grid_barrier(int id, unsigned nblocks) {
    __syncthreads();
    if (threadIdx.x == 0) {
        __threadfence();
        unsigned long long e0 = g_bar_rel[id];          // pre-release epoch
        unsigned long long a = atomicAdd(&g_bar_cnt[id], 1ULL) + 1ULL;
        if (a % (unsigned long long)nblocks == 0ULL) {
            atomicAdd((unsigned long long*)&g_bar_rel[id], 1ULL);
        } else {
            while (g_bar_rel[id] == e0) { }
        }
        __threadfence();
    }
    __syncthreads();
}

// ---------------------------------------------------------------------------
// One persistent kernel, three phases, two grid barriers.
// ---------------------------------------------------------------------------
__global__ __launch_bounds__(256) void fused_kernel(const float* __restrict__ key,
                                                    const float* __restrict__ val,
                                                    const float* __restrict__ w_k,
                                                    float4* __restrict__ out4,
                                                    float4* __restrict__ att4) {
    const int tid = threadIdx.x;
    const unsigned G = gridDim.x;

    __shared__ float s_red[8];
    __shared__ float s_stat[2];
    __shared__ float s_p[CHUNK_J];
    __shared__ float s_acc[256];
    __shared__ __align__(16) float s_buf[LK];     // 16 KB, phase D staging

    // ======================= Phase A: sk dots ============================
    {
        const int sub = tid & 7;
        const float4* wk4 = reinterpret_cast<const float4*>(w_k);
        float4 w0 = wk4[sub +  0];
        float4 w1 = wk4[sub +  8];
        float4 w2 = wk4[sub + 16];
        float4 w3 = wk4[sub + 24];
        for (int it = blockIdx.x; it < A_ITEMS; it += G) {
            int row = it * 32 + (tid >> 3);
            const float4* r4 = reinterpret_cast<const float4*>(key + (size_t)row * DD);
            float4 k0 = r4[sub +  0];
            float4 k1 = r4[sub +  8];
            float4 k2 = r4[sub + 16];
            float4 k3 = r4[sub + 24];
            float acc = k0.x * w0.x + k0.y * w0.y + k0.z * w0.z + k0.w * w0.w;
            acc += k1.x * w1.x + k1.y * w1.y + k1.z * w1.z + k1.w * w1.w;
            acc += k2.x * w2.x + k2.y * w2.y + k2.z * w2.z + k2.w * w2.w;
            acc += k3.x * w3.x + k3.y * w3.y + k3.z * w3.z + k3.w * w3.w;
            acc += __shfl_xor_sync(0xFFFFFFFFu, acc, 4);
            acc += __shfl_xor_sync(0xFFFFFFFFu, acc, 2);
            acc += __shfl_xor_sync(0xFFFFFFFFu, acc, 1);
            if (sub == 0) g_sk[row] = acc;
        }
    }

    grid_barrier(0, G);

    // ====== Phase B: softmax stats (redundant per item) + p + partials ====
    for (int w = blockIdx.x; w < B_ITEMS; w += G) {
        const int b = w >> 7;
        const int chunk = w & (NCH - 1);

        float v[16];
        float mx = -1e30f;
        #pragma unroll
        for (int r = 0; r < 16; ++r) {
            v[r] = __ldcg(&g_sk[b * LK + tid + r * 256]);
            mx = fmaxf(mx, v[r]);
        }
        #pragma unroll
        for (int o = 16; o > 0; o >>= 1) mx = fmaxf(mx, __shfl_xor_sync(0xFFFFFFFFu, mx, o));
        if ((tid & 31) == 0) s_red[tid >> 5] = mx;
        __syncthreads();
        if (tid < 8) {
            float m = s_red[tid];
            #pragma unroll
            for (int o = 4; o > 0; o >>= 1) m = fmaxf(m, __shfl_xor_sync(0xFFu, m, o));
            if (tid == 0) s_stat[0] = m;
        }
        __syncthreads();
        mx = s_stat[0];

        float sum = 0.f;
        #pragma unroll
        for (int r = 0; r < 16; ++r) sum += expf(v[r] - mx);
        #pragma unroll
        for (int o = 16; o > 0; o >>= 1) sum += __shfl_xor_sync(0xFFFFFFFFu, sum, o);
        __syncthreads();
        if ((tid & 31) == 0) s_red[tid >> 5] = sum;
        __syncthreads();
        if (tid < 8) {
            float s = s_red[tid];
            #pragma unroll
            for (int o = 4; o > 0; o >>= 1) s += __shfl_xor_sync(0xFFu, s, o);
            if (tid == 0) s_stat[1] = 1.0f / s;
        }
        __syncthreads();
        const float inv = s_stat[1];

        const int j0 = chunk * CHUNK_J;
        if (tid < CHUNK_J) {
            float p = expf(__ldcg(&g_sk[b * LK + j0 + tid]) - mx) * inv;
            s_p[tid] = p;
            g_p[b * LK + j0 + tid] = p;
        }
        __syncthreads();

        const int d = tid & (DD - 1);
        const int half = tid >> 7;                    // 16 j's per half
        const float* vbase = val + (((size_t)b * LK + j0 + half * 16) * DD) + d;
        float acc = 0.f;
        #pragma unroll 4
        for (int jj = 0; jj < 16; ++jj)
            acc += s_p[half * 16 + jj] * vbase[(size_t)jj * DD];
        s_acc[tid] = acc;
        __syncthreads();
        if (tid < DD)
            g_part[(b * NCH + chunk) * DD + tid] = s_acc[tid] + s_acc[tid + DD];
        __syncthreads();
    }

    grid_barrier(1, G);

    // ================= Phase D: att (256 MB) + out (8 MB) =================
    for (int w = blockIdx.x; w < D_ITEMS; w += G) {
        if (w < ATT_ITEMS) {
            // att item: 8 full rows of batch b = w>>9.
            const int b = w >> 9;
            float4* s_p4 = reinterpret_cast<float4*>(s_buf);
            const float4* p4 = reinterpret_cast<const float4*>(g_p) + (b << 10);
            #pragma unroll
            for (int r = 0; r < 4; ++r)
                s_p4[tid + r * 256] = __ldcg(&p4[tid + r * 256]);
            __syncthreads();
            float4* dst = att4 + (size_t)w * 8 * (LK / 4);
            #pragma unroll
            for (int rr = 0; rr < 8; ++rr) {
                #pragma unroll
                for (int r = 0; r < 4; ++r) {
                    int c = tid + r * 256;
                    __stcs(dst + (size_t)rr * (LK / 4) + c, s_p4[c]);
                }
            }
        } else {
            // out item: reduce 128 partials, broadcast 32 rows.
            const int o = w - ATT_ITEMS;              // 0..511
            const int b = o >> 7;
            if (tid < DD) {
                float s = 0.f;
                #pragma unroll 8
                for (int c = 0; c < NCH; ++c)
                    s += __ldcg(&g_part[(b * NCH + c) * DD + tid]);
                s_buf[tid] = s;
            }
            __syncthreads();
            const float4* row4 = reinterpret_cast<const float4*>(s_buf);
            size_t base = (size_t)o * 1024;
            #pragma unroll
            for (int r = 0; r < 4; ++r) {
                size_t t = base + tid + r * 256;
                __stcs(out4 + t, row4[t & 31]);       // D/4 = 32
            }
        }
        __syncthreads();                              // smem reuse
    }
}

// ---------------------------------------------------------------------------
// Inputs (metadata order): 0=qry, 1=key, 2=val, 3=w_q, 4=w_k.
// qry and w_q are mathematically irrelevant (softmax shift-invariance).
// Output: tuple (out, att) concatenated: out = B*LQ*D floats, then att.
// ---------------------------------------------------------------------------
extern "C" void kernel_launch(void* const* d_in, const int* in_sizes, int n_in,
                              void* d_out, int out_size) {
    const float* key = (const float*)d_in[1];
    const float* val = (const float*)d_in[2];
    const float* w_k = (const float*)d_in[4];
    float* out = (float*)d_out;
    float* att = out + (size_t)BB * LQ * DD;

    int dev = 0;
    cudaGetDevice(&dev);
    int sms = 0;
    cudaDeviceGetAttribute(&sms, cudaDevAttrMultiProcessorCount, dev);
    int occ = 0;
    cudaOccupancyMaxActiveBlocksPerMultiprocessor(&occ, fused_kernel, 256, 0);
    int G = sms * occ;                 // guaranteed co-resident
    if (G < 1) G = 1;
    if (G > D_ITEMS) G = D_ITEMS;

    fused_kernel<<<G, 256>>>(key, val, w_k,
                             reinterpret_cast<float4*>(out),
                             reinterpret_cast<float4*>(att));
}

// round 6
// speedup vs baseline: 1.0670x; 1.0670x over previous
#include <cuda_runtime.h>

// Problem constants (fixed by the reference setup_inputs).
#define BB 4
#define LQ 4096
#define LK 4096
#define DD 128

#define NCH 128                   // j-chunks per batch (32 j each)
#define CHUNK_J (LK / NCH)        // 32

#define A_ITEMS 512               // sk items: 32 rows each
#define B_ITEMS (BB * NCH)        // 512: (batch, chunk)

// Scratch (allocation-free rule: __device__ globals).
__device__ float g_sk[BB * LK];              // raw key scores
__device__ float g_p[BB * LK];               // softmax probabilities
__device__ float g_part[BB * NCH * DD];      // partial p·val sums

// Monotonic-epoch grid barrier state (zero-init, never reset -> replay-safe).
__device__ unsigned long long g_bar_cnt;
__device__ volatile unsigned long long g_bar_rel;

// ---------------------------------------------------------------------------
// K1: fused prep (persistent, one grid barrier).
//   Phase A: sk[b,j] = dot(key[b,j,:], w_k)   (8 MB key read)
//   Phase B: softmax stats (redundant per block, L2 reads) + p + val partials
// ---------------------------------------------------------------------------
__global__ __launch_bounds__(256) void prep_kernel(const float* __restrict__ key,
                                                   const float* __restrict__ val,
                                                   const float* __restrict__ w_k) {
    const int tid = threadIdx.x;
    const unsigned G = gridDim.x;

    __shared__ float s_red[8];
    __shared__ float s_stat[2];
    __shared__ float s_p[CHUNK_J];
    __shared__ float s_acc[256];

    // ======================= Phase A: sk dots ============================
    {
        const int sub = tid & 7;
        const float4* wk4 = reinterpret_cast<const float4*>(w_k);
        float4 w0 = wk4[sub +  0];
        float4 w1 = wk4[sub +  8];
        float4 w2 = wk4[sub + 16];
        float4 w3 = wk4[sub + 24];
        for (int it = blockIdx.x; it < A_ITEMS; it += G) {
            int row = it * 32 + (tid >> 3);
            const float4* r4 = reinterpret_cast<const float4*>(key + (size_t)row * DD);
            float4 k0 = r4[sub +  0];
            float4 k1 = r4[sub +  8];
            float4 k2 = r4[sub + 16];
            float4 k3 = r4[sub + 24];
            float acc = k0.x * w0.x + k0.y * w0.y + k0.z * w0.z + k0.w * w0.w;
            acc += k1.x * w1.x + k1.y * w1.y + k1.z * w1.z + k1.w * w1.w;
            acc += k2.x * w2.x + k2.y * w2.y + k2.z * w2.z + k2.w * w2.w;
            acc += k3.x * w3.x + k3.y * w3.y + k3.z * w3.z + k3.w * w3.w;
            acc += __shfl_xor_sync(0xFFFFFFFFu, acc, 4);
            acc += __shfl_xor_sync(0xFFFFFFFFu, acc, 2);
            acc += __shfl_xor_sync(0xFFFFFFFFu, acc, 1);
            if (sub == 0) g_sk[row] = acc;
        }
    }

    // ---- grid barrier (monotonic epoch; zero-init, replay-safe) ----
    __syncthreads();
    if (tid == 0) {
        __threadfence();
        unsigned long long e0 = g_bar_rel;
        unsigned long long a = atomicAdd(&g_bar_cnt, 1ULL) + 1ULL;
        if (a % (unsigned long long)G == 0ULL) {
            atomicAdd((unsigned long long*)&g_bar_rel, 1ULL);
        } else {
            while (g_bar_rel == e0) { }
        }
        __threadfence();
    }
    __syncthreads();

    // ====== Phase B: softmax stats + p + val partials (one chunk/block) ===
    for (int w = blockIdx.x; w < B_ITEMS; w += G) {
        const int b = w >> 7;                 // / NCH
        const int chunk = w & (NCH - 1);

        float v[16];
        float mx = -1e30f;
        #pragma unroll
        for (int r = 0; r < 16; ++r) {
            v[r] = __ldcg(&g_sk[b * LK + tid + r * 256]);
            mx = fmaxf(mx, v[r]);
        }
        #pragma unroll
        for (int o = 16; o > 0; o >>= 1) mx = fmaxf(mx, __shfl_xor_sync(0xFFFFFFFFu, mx, o));
        if ((tid & 31) == 0) s_red[tid >> 5] = mx;
        __syncthreads();
        if (tid < 8) {
            float m = s_red[tid];
            #pragma unroll
            for (int o = 4; o > 0; o >>= 1) m = fmaxf(m, __shfl_xor_sync(0xFFu, m, o));
            if (tid == 0) s_stat[0] = m;
        }
        __syncthreads();
        mx = s_stat[0];

        float sum = 0.f;
        #pragma unroll
        for (int r = 0; r < 16; ++r) sum += expf(v[r] - mx);
        #pragma unroll
        for (int o = 16; o > 0; o >>= 1) sum += __shfl_xor_sync(0xFFFFFFFFu, sum, o);
        __syncthreads();
        if ((tid & 31) == 0) s_red[tid >> 5] = sum;
        __syncthreads();
        if (tid < 8) {
            float s = s_red[tid];
            #pragma unroll
            for (int o = 4; o > 0; o >>= 1) s += __shfl_xor_sync(0xFFu, s, o);
            if (tid == 0) s_stat[1] = 1.0f / s;
        }
        __syncthreads();
        const float inv = s_stat[1];

        const int j0 = chunk * CHUNK_J;
        if (tid < CHUNK_J) {
            float p = expf(__ldcg(&g_sk[b * LK + j0 + tid]) - mx) * inv;
            s_p[tid] = p;
            g_p[b * LK + j0 + tid] = p;
        }
        __syncthreads();

        const int d = tid & (DD - 1);
        const int half = tid >> 7;                    // 16 j's per half
        const float* vbase = val + (((size_t)b * LK + j0 + half * 16) * DD) + d;
        float acc = 0.f;
        #pragma unroll 4
        for (int jj = 0; jj < 16; ++jj)
            acc += s_p[half * 16 + jj] * vbase[(size_t)jj * DD];
        s_acc[tid] = acc;
        __syncthreads();
        if (tid < DD)
            g_part[(b * NCH + chunk) * DD + tid] = s_acc[tid] + s_acc[tid + DD];
        __syncthreads();
    }
}

// ---------------------------------------------------------------------------
// K2: mega-writer (R4 structure, measured ~6 TB/s — do not perturb).
//   blocks [0, ATT_BLOCKS):  att (256 MB), 8 rows/block, shared-staged p,
//                            __stcs streaming stores. Long pole, first.
//   blocks [ATT_BLOCKS, +OUT_BLOCKS): reduce partials, write out (8 MB).
// ---------------------------------------------------------------------------
#define OUT_BLOCKS 512
#define ROWS_PER_BLK 8
#define ATT_BLOCKS (BB * LQ / ROWS_PER_BLK)   // 2048

__global__ __launch_bounds__(256) void mega_writer_kernel(float4* __restrict__ out4,
                                                          float4* __restrict__ att4) {
    const int tid = threadIdx.x;

    if (blockIdx.x < ATT_BLOCKS) {
        // ---- att writer ----
        const int bid = blockIdx.x;                    // 0 .. ATT_BLOCKS-1
        const int row0 = bid * ROWS_PER_BLK;           // global row (b*LQ + i)
        const int b = row0 >> 12;                      // / LQ

        __shared__ float4 s_p4[LK / 4];                // 16 KB: full p row
        const float4* p4 = reinterpret_cast<const float4*>(g_p) + (b << 10);
        #pragma unroll
        for (int r = 0; r < 4; ++r)
            s_p4[tid + r * 256] = p4[tid + r * 256];
        __syncthreads();

        float4* dst = att4 + (size_t)row0 * (LK / 4);
        #pragma unroll
        for (int rr = 0; rr < ROWS_PER_BLK; ++rr) {
            #pragma unroll
            for (int r = 0; r < 4; ++r) {
                int c = tid + r * 256;
                __stcs(dst + (size_t)rr * (LK / 4) + c, s_p4[c]);
            }
        }
    } else {
        // ---- out writer: 1024 float4 per block; 128 blocks per batch ----
        const int bid = blockIdx.x - ATT_BLOCKS;       // 0 .. OUT_BLOCKS-1
        const int b = bid >> 7;                        // 128 blocks per batch
        __shared__ float s_row[DD];
        if (tid < DD) {
            float s = 0.f;
            #pragma unroll 8
            for (int c = 0; c < NCH; ++c)
                s += g_part[(b * NCH + c) * DD + tid];
            s_row[tid] = s;
        }
        __syncthreads();
        const float4* row4 = reinterpret_cast<const float4*>(s_row);
        size_t base = (size_t)bid * 1024;              // float4 index into out
        #pragma unroll
        for (int r = 0; r < 4; ++r) {
            size_t t = base + tid + r * 256;
            __stcs(out4 + t, row4[t & 31]);            // D/4 = 32
        }
    }
}

// ---------------------------------------------------------------------------
// Inputs (metadata order): 0=qry, 1=key, 2=val, 3=w_q, 4=w_k.
// qry and w_q are mathematically irrelevant (softmax shift-invariance).
// Output: tuple (out, att) concatenated: out = B*LQ*D floats, then att.
// ---------------------------------------------------------------------------
extern "C" void kernel_launch(void* const* d_in, const int* in_sizes, int n_in,
                              void* d_out, int out_size) {
    const float* key = (const float*)d_in[1];
    const float* val = (const float*)d_in[2];
    const float* w_k = (const float*)d_in[4];
    float* out = (float*)d_out;
    float* att = out + (size_t)BB * LQ * DD;

    int dev = 0;
    cudaGetDevice(&dev);
    int sms = 0;
    cudaDeviceGetAttribute(&sms, cudaDevAttrMultiProcessorCount, dev);
    int occ = 0;
    cudaOccupancyMaxActiveBlocksPerMultiprocessor(&occ, prep_kernel, 256, 0);
    int G = sms * occ;                 // guaranteed co-resident
    if (G < 1) G = 1;
    if (G > A_ITEMS) G = A_ITEMS;      // A_ITEMS == B_ITEMS == 512

    prep_kernel<<<G, 256>>>(key, val, w_k);
    mega_writer_kernel<<<ATT_BLOCKS + OUT_BLOCKS, 256>>>(
        reinterpret_cast<float4*>(out), reinterpret_cast<float4*>(att));
}